// round 3
// baseline (speedup 1.0000x reference)
#include <cuda_runtime.h>
#include <cuda_fp16.h>
#include <math.h>

#define Bb 8
#define Hh 16
#define Nn 512
#define Dk 64
#define Dm 1024
#define LOG2E 1.44269504088896f

__device__ float g_q[Bb*Hh*Nn*Dk];
__device__ float g_k[Bb*Hh*Nn*Dk];
__device__ float g_v[Bb*Hh*Nn*Dk];
__device__ __half g_g16[(size_t)Bb*Hh*Nn*Nn];   // 268 MB: g = max(relu(.),1e-6), (b,h,i,j)
__device__ float g_attn[Bb*Nn*Hh*Dk];

// ---------------- SGEMM (unchanged from R1): C[4096,1024] = A @ W^T + bias --
__global__ __launch_bounds__(256) void sgemm_tn(const float* __restrict__ A,
                                                const float* __restrict__ W,
                                                const float* __restrict__ bias,
                                                float* __restrict__ C, int remap) {
    __shared__ float As[8][128];
    __shared__ float Bs[8][128];
    int tid = threadIdx.x;
    int tx = tid & 15, ty = tid >> 4;
    int m0 = blockIdx.y * 128, n0 = blockIdx.x * 128;
    int lr = tid >> 1, lc = (tid & 1) * 4;
    const float* Ap = A + (size_t)(m0 + lr) * 1024 + lc;
    const float* Wp = W + (size_t)(n0 + lr) * 1024 + lc;

    float acc[8][8];
#pragma unroll
    for (int i = 0; i < 8; i++)
#pragma unroll
        for (int j = 0; j < 8; j++) acc[i][j] = 0.f;

    for (int kt = 0; kt < 128; kt++) {
        float4 av = *(const float4*)(Ap + kt * 8);
        float4 wv = *(const float4*)(Wp + kt * 8);
        __syncthreads();
        As[lc+0][lr]=av.x; As[lc+1][lr]=av.y; As[lc+2][lr]=av.z; As[lc+3][lr]=av.w;
        Bs[lc+0][lr]=wv.x; Bs[lc+1][lr]=wv.y; Bs[lc+2][lr]=wv.z; Bs[lc+3][lr]=wv.w;
        __syncthreads();
#pragma unroll
        for (int kk = 0; kk < 8; kk++) {
            float4 a0 = *(const float4*)&As[kk][ty*4];
            float4 a1 = *(const float4*)&As[kk][64+ty*4];
            float4 b0 = *(const float4*)&Bs[kk][tx*4];
            float4 b1 = *(const float4*)&Bs[kk][64+tx*4];
            float af[8] = {a0.x,a0.y,a0.z,a0.w,a1.x,a1.y,a1.z,a1.w};
            float bf[8] = {b0.x,b0.y,b0.z,b0.w,b1.x,b1.y,b1.z,b1.w};
#pragma unroll
            for (int i = 0; i < 8; i++)
#pragma unroll
                for (int j = 0; j < 8; j++) acc[i][j] += af[i]*bf[j];
        }
    }
#pragma unroll
    for (int i = 0; i < 8; i++) {
        int mrow = m0 + ((i < 4) ? (ty*4+i) : (64+ty*4+(i-4)));
#pragma unroll
        for (int jq = 0; jq < 2; jq++) {
            int ncol = n0 + ((jq==0) ? (tx*4) : (64+tx*4));
            float4 v;
            v.x = acc[i][jq*4+0]+bias[ncol+0]; v.y = acc[i][jq*4+1]+bias[ncol+1];
            v.z = acc[i][jq*4+2]+bias[ncol+2]; v.w = acc[i][jq*4+3]+bias[ncol+3];
            if (remap) {
                int bb = mrow>>9, n = mrow&511, hh = ncol>>6, d = ncol&63;
                *(float4*)&C[(((size_t)bb*Hh+hh)*Nn+n)*Dk+d] = v;
            } else {
                *(float4*)&C[(size_t)mrow*1024+ncol] = v;
            }
        }
    }
}

// ---------------- geometry bias -> fp16 g (no log) -------------------------
__global__ __launch_bounds__(256) void geo_bias_kernel(const float* __restrict__ boxes,
                                                       const float* __restrict__ Wg,
                                                       const float* __restrict__ bg) {
    __shared__ float Wsin[32][16];
    __shared__ float Wcos[32][16];
    __shared__ float bgs[16];
    int i = blockIdx.x, b = blockIdx.y;
    int tid = threadIdx.x;

    for (int t = tid; t < Hh*64; t += 256) {
        int h = t >> 6, d = t & 63;
        float w = Wg[h*64+d];
        if (d < 32) Wsin[d][h] = w; else Wcos[d-32][h] = w;
    }
    if (tid < 16) bgs[tid] = bg[tid];

    const float* pbi = boxes + ((size_t)b*Nn+i)*4;
    float xi0=pbi[0], yi0=pbi[1], xi1=pbi[2], yi1=pbi[3];
    float cxi=0.5f*(xi0+xi1), cyi=0.5f*(yi0+yi1);
    float wi=xi1-xi0+1.0f, hi=yi1-yi0+1.0f;
    float lwi=__logf(wi), lhi=__logf(hi);
    __syncthreads();

    const float dm[8] = {1.0f,0.421696503429f,0.177827941004f,0.0749894209332f,
                         0.0316227766017f,0.0133352143216f,0.00562341325190f,0.00237137370566f};

    for (int j = tid; j < Nn; j += 256) {
        const float* pbj = boxes + ((size_t)b*Nn+j)*4;
        float xj0=pbj[0], yj0=pbj[1], xj1=pbj[2], yj1=pbj[3];
        float cxj=0.5f*(xj0+xj1), cyj=0.5f*(yj0+yj1);
        float wj=xj1-xj0+1.0f, hj=yj1-yj0+1.0f;

        float pos[4];
        pos[0] = __logf(fmaxf(fabsf((cxi-cxj)/wi), 1e-3f));
        pos[1] = __logf(fmaxf(fabsf((cyi-cyj)/hi), 1e-3f));
        pos[2] = lwi - __logf(wj);
        pos[3] = lhi - __logf(hj);

        float sv[32], cv[32];
#pragma unroll
        for (int c = 0; c < 4; c++) {
            float base = 100.0f*pos[c];
#pragma unroll
            for (int f = 0; f < 8; f++)
                __sincosf(base*dm[f], &sv[c*8+f], &cv[c*8+f]);
        }

        float acc[16];
#pragma unroll
        for (int h = 0; h < 16; h++) acc[h] = bgs[h];
#pragma unroll
        for (int idx = 0; idx < 32; idx++) {
            float s = sv[idx], c = cv[idx];
#pragma unroll
            for (int hq = 0; hq < 4; hq++) {
                float4 ws = *(const float4*)&Wsin[idx][hq*4];
                float4 wc = *(const float4*)&Wcos[idx][hq*4];
                acc[hq*4+0] += s*ws.x + c*wc.x;
                acc[hq*4+1] += s*ws.y + c*wc.y;
                acc[hq*4+2] += s*ws.z + c*wc.z;
                acc[hq*4+3] += s*ws.w + c*wc.w;
            }
        }
#pragma unroll
        for (int h = 0; h < 16; h++)
            g_g16[(((size_t)b*Hh+h)*Nn+i)*Nn+j] = __float2half_rn(fmaxf(acc[h], 1e-6f));
    }
}

// ---------------- flash attention with multiplicative fp16 bias g ----------
// block: 64 q rows of one (b,h); 256 thr (tx=tid&15 -> 4k/4d cols, ty=tid>>4 -> 4q rows)
// smem: Qs[d][68] Kt[d][68] Vt[k][68] Pt[k][68] = 69632 B
__global__ __launch_bounds__(256) void attn_kernel(int bh0) {
    extern __shared__ float sh[];
    float* Qs = sh;                // d-major: Qs[d*68+q]
    float* Kt = sh + 64*68;        // d-major: Kt[d*68+k]
    float* Vt = Kt + 64*68;        // k-major: Vt[k*68+d]
    float* Pt = Vt + 64*68;        // k-major: Pt[k*68+q]

    int bh = bh0 + blockIdx.y;
    int b = bh >> 4, h = bh & 15;
    int q0 = blockIdx.x * 64;
    const float* Qg = g_q + ((size_t)bh*Nn + q0)*Dk;
    const float* Kg = g_k + (size_t)bh*Nn*Dk;
    const float* Vg = g_v + (size_t)bh*Nn*Dk;
    const __half* Gg = g_g16 + ((size_t)bh*Nn + q0)*Nn;

    int tid = threadIdx.x;
    int tx = tid & 15, ty = tid >> 4;

    // Q transpose into smem (4x4 micro-transpose)
    {
        int qq0 = tx*4, dd0 = ty*4;
        float4 r0 = *(const float4*)&Qg[(qq0+0)*64+dd0];
        float4 r1 = *(const float4*)&Qg[(qq0+1)*64+dd0];
        float4 r2 = *(const float4*)&Qg[(qq0+2)*64+dd0];
        float4 r3 = *(const float4*)&Qg[(qq0+3)*64+dd0];
        *(float4*)&Qs[(dd0+0)*68+qq0] = make_float4(r0.x,r1.x,r2.x,r3.x);
        *(float4*)&Qs[(dd0+1)*68+qq0] = make_float4(r0.y,r1.y,r2.y,r3.y);
        *(float4*)&Qs[(dd0+2)*68+qq0] = make_float4(r0.z,r1.z,r2.z,r3.z);
        *(float4*)&Qs[(dd0+3)*68+qq0] = make_float4(r0.w,r1.w,r2.w,r3.w);
    }

    float m[4], l[4], o[4][4];
#pragma unroll
    for (int i = 0; i < 4; i++) {
        m[i] = -1e30f; l[i] = 0.f;
#pragma unroll
        for (int j = 0; j < 4; j++) o[i][j] = 0.f;
    }

    for (int kt = 0; kt < 8; kt++) {
        __syncthreads();   // prior-iter reads of Kt/Vt/Pt done (covers Qs on iter 0)
        {   // K transpose load
            int kk0 = tx*4, dd0 = ty*4;
            const float* Kb = Kg + (size_t)(kt*64)*Dk;
            float4 r0 = *(const float4*)&Kb[(kk0+0)*64+dd0];
            float4 r1 = *(const float4*)&Kb[(kk0+1)*64+dd0];
            float4 r2 = *(const float4*)&Kb[(kk0+2)*64+dd0];
            float4 r3 = *(const float4*)&Kb[(kk0+3)*64+dd0];
            *(float4*)&Kt[(dd0+0)*68+kk0] = make_float4(r0.x,r1.x,r2.x,r3.x);
            *(float4*)&Kt[(dd0+1)*68+kk0] = make_float4(r0.y,r1.y,r2.y,r3.y);
            *(float4*)&Kt[(dd0+2)*68+kk0] = make_float4(r0.z,r1.z,r2.z,r3.z);
            *(float4*)&Kt[(dd0+3)*68+kk0] = make_float4(r0.w,r1.w,r2.w,r3.w);
        }
        for (int i = tid; i < 1024; i += 256) {   // V natural load
            int r = i >> 4, c = (i & 15)*4;
            *(float4*)&Vt[r*68+c] = *(const float4*)&Vg[(size_t)(kt*64+r)*64+c];
        }
        __syncthreads();

        // S = Q.K^T (4q x 4k per thread)
        float acc[4][4];
#pragma unroll
        for (int i = 0; i < 4; i++)
#pragma unroll
            for (int j = 0; j < 4; j++) acc[i][j] = 0.f;
#pragma unroll 4
        for (int d = 0; d < 64; d++) {
            float4 qv = *(const float4*)&Qs[d*68+ty*4];
            float4 kv = *(const float4*)&Kt[d*68+tx*4];
            float qa[4] = {qv.x,qv.y,qv.z,qv.w};
            float ka[4] = {kv.x,kv.y,kv.z,kv.w};
#pragma unroll
            for (int i = 0; i < 4; i++)
#pragma unroll
                for (int j = 0; j < 4; j++) acc[i][j] += qa[i]*ka[j];
        }

        // online softmax with multiplicative g
        float w[4][4];
#pragma unroll
        for (int qq = 0; qq < 4; qq++) {
            float s0 = acc[qq][0]*0.125f, s1 = acc[qq][1]*0.125f;
            float s2 = acc[qq][2]*0.125f, s3 = acc[qq][3]*0.125f;
            float mt = fmaxf(fmaxf(s0,s1), fmaxf(s2,s3));
#pragma unroll
            for (int off = 1; off < 16; off <<= 1)
                mt = fmaxf(mt, __shfl_xor_sync(0xffffffffu, mt, off, 16));
            float mn = fmaxf(m[qq], mt);
            float resc = exp2f((m[qq]-mn)*LOG2E);
            m[qq] = mn;
            l[qq] *= resc;
            o[qq][0]*=resc; o[qq][1]*=resc; o[qq][2]*=resc; o[qq][3]*=resc;

            const __half* gp = Gg + (size_t)(ty*4+qq)*Nn + kt*64 + tx*4;
            float2 g01 = __half22float2(*(const __half2*)gp);
            float2 g23 = __half22float2(*(const __half2*)(gp+2));
            w[qq][0] = g01.x * exp2f((s0-mn)*LOG2E);
            w[qq][1] = g01.y * exp2f((s1-mn)*LOG2E);
            w[qq][2] = g23.x * exp2f((s2-mn)*LOG2E);
            w[qq][3] = g23.y * exp2f((s3-mn)*LOG2E);
            float ps = w[qq][0]+w[qq][1]+w[qq][2]+w[qq][3];
#pragma unroll
            for (int off = 1; off < 16; off <<= 1)
                ps += __shfl_xor_sync(0xffffffffu, ps, off, 16);
            l[qq] += ps;
        }
#pragma unroll
        for (int kk = 0; kk < 4; kk++)
            *(float4*)&Pt[(tx*4+kk)*68 + ty*4] =
                make_float4(w[0][kk], w[1][kk], w[2][kk], w[3][kk]);
        __syncthreads();

        // O += P.V (4q x 4d per thread)
#pragma unroll 4
        for (int k = 0; k < 64; k++) {
            float4 pv = *(const float4*)&Pt[k*68+ty*4];
            float4 vv = *(const float4*)&Vt[k*68+tx*4];
            float pa[4] = {pv.x,pv.y,pv.z,pv.w};
            float va[4] = {vv.x,vv.y,vv.z,vv.w};
#pragma unroll
            for (int i = 0; i < 4; i++)
#pragma unroll
                for (int j = 0; j < 4; j++) o[i][j] += pa[i]*va[j];
        }
    }

#pragma unroll
    for (int qq = 0; qq < 4; qq++) {
        float inv = 1.0f / l[qq];
        int row = q0 + ty*4 + qq;
        *(float4*)&g_attn[((size_t)b*Nn+row)*Dm + h*64 + tx*4] =
            make_float4(o[qq][0]*inv, o[qq][1]*inv, o[qq][2]*inv, o[qq][3]*inv);
    }
}

// ---------------------------------------------------------------------------
extern "C" void kernel_launch(void* const* d_in, const int* in_sizes, int n_in,
                              void* d_out, int out_size) {
    (void)in_sizes; (void)n_in; (void)out_size;
    const float* queries = (const float*)d_in[0];
    const float* keys    = (const float*)d_in[1];
    const float* values  = (const float*)d_in[2];
    const float* boxes   = (const float*)d_in[3];
    const float* Wq = (const float*)d_in[4];
    const float* bq = (const float*)d_in[5];
    const float* Wk = (const float*)d_in[6];
    const float* bk = (const float*)d_in[7];
    const float* Wv = (const float*)d_in[8];
    const float* bv = (const float*)d_in[9];
    const float* Wo = (const float*)d_in[10];
    const float* bo = (const float*)d_in[11];
    const float* Wg = (const float*)d_in[12];
    const float* bg = (const float*)d_in[13];
    float* out = (float*)d_out;

    float *dq=nullptr, *dk=nullptr, *dv=nullptr, *dattn=nullptr;
    cudaGetSymbolAddress((void**)&dq, g_q);
    cudaGetSymbolAddress((void**)&dk, g_k);
    cudaGetSymbolAddress((void**)&dv, g_v);
    cudaGetSymbolAddress((void**)&dattn, g_attn);

    size_t shb = (size_t)4*64*68*sizeof(float);   // 69632
    cudaFuncSetAttribute(attn_kernel, cudaFuncAttributeMaxDynamicSharedMemorySize, (int)shb);

    dim3 gemm_grid(Dm/128, (Bb*Nn)/128);

    geo_bias_kernel<<<dim3(Nn, Bb), 256>>>(boxes, Wg, bg);
    sgemm_tn<<<gemm_grid, 256>>>(queries, Wq, bq, dq, 1);
    sgemm_tn<<<gemm_grid, 256>>>(keys,    Wk, bk, dk, 1);
    sgemm_tn<<<gemm_grid, 256>>>(values,  Wv, bv, dv, 1);
    attn_kernel<<<dim3(Nn/64, 64), 256, shb>>>(0);    // bh 0..63
    attn_kernel<<<dim3(Nn/64, 64), 256, shb>>>(64);   // bh 64..127  <- ncu slot
    sgemm_tn<<<gemm_grid, 256>>>(dattn, Wo, bo, out, 0);
}

// round 4
// speedup vs baseline: 1.4272x; 1.4272x over previous
#include <cuda_runtime.h>
#include <cuda_fp16.h>
#include <math.h>

#define Bb 8
#define Hh 16
#define Nn 512
#define Dk 64
#define Dm 1024

typedef unsigned long long ull;

__device__ __forceinline__ ull f2dup(float a) {
    ull r; asm("mov.b64 %0,{%1,%1};" : "=l"(r) : "f"(a)); return r;
}
__device__ __forceinline__ float2 unpack2(ull a) {
    float2 f; asm("mov.b64 {%0,%1},%2;" : "=f"(f.x), "=f"(f.y) : "l"(a)); return f;
}
__device__ __forceinline__ ull ffma2(ull a, ull b, ull c) {
    ull d; asm("fma.rn.f32x2 %0,%1,%2,%3;" : "=l"(d) : "l"(a), "l"(b), "l"(c)); return d;
}
__device__ __forceinline__ ull fmul2(ull a, ull b) {
    ull d; asm("mul.rn.f32x2 %0,%1,%2;" : "=l"(d) : "l"(a), "l"(b)); return d;
}

__device__ float g_q[Bb*Hh*Nn*Dk];
__device__ float g_k[Bb*Hh*Nn*Dk];
__device__ float g_v[Bb*Hh*Nn*Dk];
__device__ __half g_g16[(size_t)Bb*Hh*Nn*Nn];   // g = max(relu(.),1e-6), (b,h,i,j)
__device__ float g_attn[Bb*Nn*Hh*Dk];

// ---------------- SGEMM with FFMA2 micro-kernel ----------------------------
__global__ __launch_bounds__(256) void sgemm_tn(const float* __restrict__ A,
                                                const float* __restrict__ W,
                                                const float* __restrict__ bias,
                                                float* __restrict__ C, int remap) {
    __shared__ __align__(16) float As[8][128];
    __shared__ __align__(16) float Bs[8][128];
    int tid = threadIdx.x;
    int tx = tid & 15, ty = tid >> 4;
    int m0 = blockIdx.y * 128, n0 = blockIdx.x * 128;
    int lr = tid >> 1, lc = (tid & 1) * 4;
    const float* Ap = A + (size_t)(m0 + lr) * 1024 + lc;
    const float* Wp = W + (size_t)(n0 + lr) * 1024 + lc;

    ull acc[8][4];
#pragma unroll
    for (int i = 0; i < 8; i++)
#pragma unroll
        for (int p = 0; p < 4; p++) acc[i][p] = 0ull;

    for (int kt = 0; kt < 128; kt++) {
        float4 av = *(const float4*)(Ap + kt * 8);
        float4 wv = *(const float4*)(Wp + kt * 8);
        __syncthreads();
        As[lc+0][lr]=av.x; As[lc+1][lr]=av.y; As[lc+2][lr]=av.z; As[lc+3][lr]=av.w;
        Bs[lc+0][lr]=wv.x; Bs[lc+1][lr]=wv.y; Bs[lc+2][lr]=wv.z; Bs[lc+3][lr]=wv.w;
        __syncthreads();
#pragma unroll
        for (int kk = 0; kk < 8; kk++) {
            float4 a0 = *(const float4*)&As[kk][ty*4];
            float4 a1 = *(const float4*)&As[kk][64+ty*4];
            ull ad[8] = {f2dup(a0.x),f2dup(a0.y),f2dup(a0.z),f2dup(a0.w),
                         f2dup(a1.x),f2dup(a1.y),f2dup(a1.z),f2dup(a1.w)};
            ulonglong2 b0 = *(const ulonglong2*)&Bs[kk][tx*4];
            ulonglong2 b1 = *(const ulonglong2*)&Bs[kk][64+tx*4];
            ull bp[4] = {b0.x, b0.y, b1.x, b1.y};
#pragma unroll
            for (int i = 0; i < 8; i++)
#pragma unroll
                for (int p = 0; p < 4; p++)
                    acc[i][p] = ffma2(ad[i], bp[p], acc[i][p]);
        }
    }
#pragma unroll
    for (int i = 0; i < 8; i++) {
        int mrow = m0 + ((i < 4) ? (ty*4+i) : (64+ty*4+(i-4)));
#pragma unroll
        for (int jq = 0; jq < 2; jq++) {
            int ncol = n0 + ((jq==0) ? (tx*4) : (64+tx*4));
            float2 u0 = unpack2(acc[i][jq*2+0]);
            float2 u1 = unpack2(acc[i][jq*2+1]);
            float4 v;
            v.x = u0.x + bias[ncol+0]; v.y = u0.y + bias[ncol+1];
            v.z = u1.x + bias[ncol+2]; v.w = u1.y + bias[ncol+3];
            if (remap) {
                int bb = mrow>>9, n = mrow&511, hh = ncol>>6, d = ncol&63;
                *(float4*)&C[(((size_t)bb*Hh+hh)*Nn+n)*Dk+d] = v;
            } else {
                *(float4*)&C[(size_t)mrow*1024+ncol] = v;
            }
        }
    }
}

// ---------------- geometry bias -> fp16 g ----------------------------------
__global__ __launch_bounds__(256) void geo_bias_kernel(const float* __restrict__ boxes,
                                                       const float* __restrict__ Wg,
                                                       const float* __restrict__ bg) {
    __shared__ __align__(16) float Wsin[32][16];
    __shared__ __align__(16) float Wcos[32][16];
    __shared__ float bgs[16];
    int i = blockIdx.x, b = blockIdx.y;
    int tid = threadIdx.x;

    for (int t = tid; t < Hh*64; t += 256) {
        int h = t >> 6, d = t & 63;
        float w = Wg[h*64+d];
        if (d < 32) Wsin[d][h] = w; else Wcos[d-32][h] = w;
    }
    if (tid < 16) bgs[tid] = bg[tid];

    const float* pbi = boxes + ((size_t)b*Nn+i)*4;
    float xi0=pbi[0], yi0=pbi[1], xi1=pbi[2], yi1=pbi[3];
    float cxi=0.5f*(xi0+xi1), cyi=0.5f*(yi0+yi1);
    float wi=xi1-xi0+1.0f, hi=yi1-yi0+1.0f;
    float lwi=__logf(wi), lhi=__logf(hi);
    float rwi=1.0f/wi, rhi=1.0f/hi;
    __syncthreads();

    const float dm[8] = {1.0f,0.421696503429f,0.177827941004f,0.0749894209332f,
                         0.0316227766017f,0.0133352143216f,0.00562341325190f,0.00237137370566f};

    for (int j = tid; j < Nn; j += 256) {
        const float* pbj = boxes + ((size_t)b*Nn+j)*4;
        float xj0=pbj[0], yj0=pbj[1], xj1=pbj[2], yj1=pbj[3];
        float cxj=0.5f*(xj0+xj1), cyj=0.5f*(yj0+yj1);
        float wj=xj1-xj0+1.0f, hj=yj1-yj0+1.0f;

        float pos[4];
        pos[0] = __logf(fmaxf(fabsf((cxi-cxj)*rwi), 1e-3f));
        pos[1] = __logf(fmaxf(fabsf((cyi-cyj)*rhi), 1e-3f));
        pos[2] = lwi - __logf(wj);
        pos[3] = lhi - __logf(hj);

        float sv[32], cv[32];
#pragma unroll
        for (int c = 0; c < 4; c++) {
            float base = 100.0f*pos[c];
#pragma unroll
            for (int f = 0; f < 8; f++)
                __sincosf(base*dm[f], &sv[c*8+f], &cv[c*8+f]);
        }

        float acc[16];
#pragma unroll
        for (int h = 0; h < 16; h++) acc[h] = bgs[h];
#pragma unroll
        for (int idx = 0; idx < 32; idx++) {
            float s = sv[idx], c = cv[idx];
#pragma unroll
            for (int hq = 0; hq < 4; hq++) {
                float4 ws = *(const float4*)&Wsin[idx][hq*4];
                float4 wc = *(const float4*)&Wcos[idx][hq*4];
                acc[hq*4+0] += s*ws.x + c*wc.x;
                acc[hq*4+1] += s*ws.y + c*wc.y;
                acc[hq*4+2] += s*ws.z + c*wc.z;
                acc[hq*4+3] += s*ws.w + c*wc.w;
            }
        }
#pragma unroll
        for (int h = 0; h < 16; h++)
            g_g16[(((size_t)b*Hh+h)*Nn+i)*Nn+j] = __float2half_rn(fmaxf(acc[h], 1e-6f));
    }
}

// ---------------- flash attention, FFMA2, 128q x 64k tile ------------------
// 128 threads: tx = tid&7 (8 k / 8 d cols), qs = tid>>3 (8 q rows each).
// smem: Qs[64][132] d-major | Kt[64][68] d-major | Vt[64][68] k-major |
//       Ptq [q][72 + pad 8 per 8 rows]  (conflict-free broadcast reads)
#define PT_RO(q) ((q)*72 + ((q)>>3)*8)
__global__ __launch_bounds__(128) void attn_kernel(int bh0) {
    extern __shared__ float sh[];
    float* Qs  = sh;                    // [d*132 + q]
    float* Kt  = sh + 64*132;           // [d*68 + k]
    float* Vt  = Kt + 64*68;            // [k*68 + d]
    float* Ptq = Vt + 64*68;            // [PT_RO(q) + k]

    int bh = bh0 + blockIdx.y;
    int b = bh >> 4, h = bh & 15;
    int q0 = blockIdx.x * 128;
    const float* Qg = g_q + ((size_t)bh*Nn + q0)*Dk;
    const float* Kg = g_k + (size_t)bh*Nn*Dk;
    const float* Vg = g_v + (size_t)bh*Nn*Dk;
    const __half* Gg = g_g16 + ((size_t)bh*Nn + q0)*Nn;

    int tid = threadIdx.x;
    int tx = tid & 7, qs = tid >> 3;

    // Q transpose: 128q x 64d -> Qs[d][q]
    for (int tt = tid; tt < 512; tt += 128) {
        int qb = (tt & 31)*4, d0 = (tt >> 5)*4;
        float4 r0 = *(const float4*)&Qg[(qb+0)*64+d0];
        float4 r1 = *(const float4*)&Qg[(qb+1)*64+d0];
        float4 r2 = *(const float4*)&Qg[(qb+2)*64+d0];
        float4 r3 = *(const float4*)&Qg[(qb+3)*64+d0];
        *(float4*)&Qs[(d0+0)*132+qb] = make_float4(r0.x,r1.x,r2.x,r3.x);
        *(float4*)&Qs[(d0+1)*132+qb] = make_float4(r0.y,r1.y,r2.y,r3.y);
        *(float4*)&Qs[(d0+2)*132+qb] = make_float4(r0.z,r1.z,r2.z,r3.z);
        *(float4*)&Qs[(d0+3)*132+qb] = make_float4(r0.w,r1.w,r2.w,r3.w);
    }

    float m[8], l[8];
    ull o[8][4];
#pragma unroll
    for (int i = 0; i < 8; i++) {
        m[i] = -1e30f; l[i] = 0.f;
#pragma unroll
        for (int p = 0; p < 4; p++) o[i][p] = 0ull;
    }
    int ro[8];
#pragma unroll
    for (int qq = 0; qq < 8; qq++) ro[qq] = PT_RO(qs*8+qq);

    for (int kt = 0; kt < 8; kt++) {
        __syncthreads();
        // K transpose: 64k x 64d -> Kt[d][k]
        for (int tt = tid; tt < 256; tt += 128) {
            int kb = (tt & 15)*4, d0 = (tt >> 4)*4;
            const float* Kb = Kg + (size_t)(kt*64)*Dk;
            float4 r0 = *(const float4*)&Kb[(kb+0)*64+d0];
            float4 r1 = *(const float4*)&Kb[(kb+1)*64+d0];
            float4 r2 = *(const float4*)&Kb[(kb+2)*64+d0];
            float4 r3 = *(const float4*)&Kb[(kb+3)*64+d0];
            *(float4*)&Kt[(d0+0)*68+kb] = make_float4(r0.x,r1.x,r2.x,r3.x);
            *(float4*)&Kt[(d0+1)*68+kb] = make_float4(r0.y,r1.y,r2.y,r3.y);
            *(float4*)&Kt[(d0+2)*68+kb] = make_float4(r0.z,r1.z,r2.z,r3.z);
            *(float4*)&Kt[(d0+3)*68+kb] = make_float4(r0.w,r1.w,r2.w,r3.w);
        }
        for (int i = tid; i < 1024; i += 128) {   // V natural
            int r = i >> 4, c = (i & 15)*4;
            *(float4*)&Vt[r*68+c] = *(const float4*)&Vg[(size_t)(kt*64+r)*64+c];
        }
        __syncthreads();

        // S = Q.K^T : 8q x 8k (4 k-pairs) per thread
        ull acc[8][4];
#pragma unroll
        for (int i = 0; i < 8; i++)
#pragma unroll
            for (int p = 0; p < 4; p++) acc[i][p] = 0ull;
#pragma unroll 2
        for (int d = 0; d < 64; d++) {
            float4 a0 = *(const float4*)&Qs[d*132 + qs*8];
            float4 a1 = *(const float4*)&Qs[d*132 + qs*8 + 4];
            ull qd[8] = {f2dup(a0.x),f2dup(a0.y),f2dup(a0.z),f2dup(a0.w),
                         f2dup(a1.x),f2dup(a1.y),f2dup(a1.z),f2dup(a1.w)};
            ulonglong2 k0 = *(const ulonglong2*)&Kt[d*68 + tx*8];
            ulonglong2 k1 = *(const ulonglong2*)&Kt[d*68 + tx*8 + 4];
            ull kp[4] = {k0.x, k0.y, k1.x, k1.y};
#pragma unroll
            for (int i = 0; i < 8; i++)
#pragma unroll
                for (int p = 0; p < 4; p++)
                    acc[i][p] = ffma2(qd[i], kp[p], acc[i][p]);
        }

        // online softmax with multiplicative fp16 g
#pragma unroll
        for (int qq = 0; qq < 8; qq++) {
            float s[8];
#pragma unroll
            for (int p = 0; p < 4; p++) {
                float2 u = unpack2(acc[qq][p]);
                s[2*p] = u.x*0.125f; s[2*p+1] = u.y*0.125f;
            }
            float mt = s[0];
#pragma unroll
            for (int j = 1; j < 8; j++) mt = fmaxf(mt, s[j]);
            mt = fmaxf(mt, __shfl_xor_sync(0xffffffffu, mt, 1, 8));
            mt = fmaxf(mt, __shfl_xor_sync(0xffffffffu, mt, 2, 8));
            mt = fmaxf(mt, __shfl_xor_sync(0xffffffffu, mt, 4, 8));
            float mn = fmaxf(m[qq], mt);
            float resc = __expf(m[qq] - mn);
            m[qq] = mn;
            l[qq] *= resc;
            ull rd = f2dup(resc);
#pragma unroll
            for (int p = 0; p < 4; p++) o[qq][p] = fmul2(o[qq][p], rd);

            const __half* gp = Gg + (size_t)(qs*8+qq)*Nn + kt*64 + tx*8;
            uint4 gv = *(const uint4*)gp;
            float2 g0 = __half22float2(*(__half2*)&gv.x);
            float2 g1 = __half22float2(*(__half2*)&gv.y);
            float2 g2 = __half22float2(*(__half2*)&gv.z);
            float2 g3 = __half22float2(*(__half2*)&gv.w);
            float w0 = g0.x*__expf(s[0]-mn), w1 = g0.y*__expf(s[1]-mn);
            float w2 = g1.x*__expf(s[2]-mn), w3 = g1.y*__expf(s[3]-mn);
            float w4 = g2.x*__expf(s[4]-mn), w5 = g2.y*__expf(s[5]-mn);
            float w6 = g3.x*__expf(s[6]-mn), w7 = g3.y*__expf(s[7]-mn);
            float ps = ((w0+w1)+(w2+w3)) + ((w4+w5)+(w6+w7));
            ps += __shfl_xor_sync(0xffffffffu, ps, 1, 8);
            ps += __shfl_xor_sync(0xffffffffu, ps, 2, 8);
            ps += __shfl_xor_sync(0xffffffffu, ps, 4, 8);
            l[qq] += ps;
            *(float4*)&Ptq[ro[qq] + tx*8]     = make_float4(w0,w1,w2,w3);
            *(float4*)&Ptq[ro[qq] + tx*8 + 4] = make_float4(w4,w5,w6,w7);
        }
        __syncthreads();

        // O += P.V : 8q x 8d (4 d-pairs) per thread
#pragma unroll 2
        for (int k = 0; k < 64; k++) {
            ull pd[8];
#pragma unroll
            for (int qq = 0; qq < 8; qq++) pd[qq] = f2dup(Ptq[ro[qq] + k]);
            ulonglong2 v0 = *(const ulonglong2*)&Vt[k*68 + tx*8];
            ulonglong2 v1 = *(const ulonglong2*)&Vt[k*68 + tx*8 + 4];
            ull vp[4] = {v0.x, v0.y, v1.x, v1.y};
#pragma unroll
            for (int i = 0; i < 8; i++)
#pragma unroll
                for (int p = 0; p < 4; p++)
                    o[i][p] = ffma2(pd[i], vp[p], o[i][p]);
        }
    }

#pragma unroll
    for (int qq = 0; qq < 8; qq++) {
        float inv = 1.0f / l[qq];
        int row = q0 + qs*8 + qq;
        float2 u0 = unpack2(o[qq][0]), u1 = unpack2(o[qq][1]);
        float2 u2 = unpack2(o[qq][2]), u3 = unpack2(o[qq][3]);
        size_t base = ((size_t)b*Nn+row)*Dm + h*64 + tx*8;
        *(float4*)&g_attn[base]   = make_float4(u0.x*inv, u0.y*inv, u1.x*inv, u1.y*inv);
        *(float4*)&g_attn[base+4] = make_float4(u2.x*inv, u2.y*inv, u3.x*inv, u3.y*inv);
    }
}

// ---------------------------------------------------------------------------
extern "C" void kernel_launch(void* const* d_in, const int* in_sizes, int n_in,
                              void* d_out, int out_size) {
    (void)in_sizes; (void)n_in; (void)out_size;
    const float* queries = (const float*)d_in[0];
    const float* keys    = (const float*)d_in[1];
    const float* values  = (const float*)d_in[2];
    const float* boxes   = (const float*)d_in[3];
    const float* Wq = (const float*)d_in[4];
    const float* bq = (const float*)d_in[5];
    const float* Wk = (const float*)d_in[6];
    const float* bk = (const float*)d_in[7];
    const float* Wv = (const float*)d_in[8];
    const float* bv = (const float*)d_in[9];
    const float* Wo = (const float*)d_in[10];
    const float* bo = (const float*)d_in[11];
    const float* Wg = (const float*)d_in[12];
    const float* bg = (const float*)d_in[13];
    float* out = (float*)d_out;

    float *dq=nullptr, *dk=nullptr, *dv=nullptr, *dattn=nullptr;
    cudaGetSymbolAddress((void**)&dq, g_q);
    cudaGetSymbolAddress((void**)&dk, g_k);
    cudaGetSymbolAddress((void**)&dv, g_v);
    cudaGetSymbolAddress((void**)&dattn, g_attn);

    // smem: Qs 64*132 + Kt 64*68 + Vt 64*68 + Ptq (128*72 + 16*8)
    size_t shb = (size_t)(64*132 + 64*68 + 64*68 + 128*72 + 128) * sizeof(float);
    cudaFuncSetAttribute(attn_kernel, cudaFuncAttributeMaxDynamicSharedMemorySize, (int)shb);

    dim3 gemm_grid(Dm/128, (Bb*Nn)/128);

    geo_bias_kernel<<<dim3(Nn, Bb), 256>>>(boxes, Wg, bg);
    sgemm_tn<<<gemm_grid, 256>>>(queries, Wq, bq, dq, 1);
    sgemm_tn<<<gemm_grid, 256>>>(keys,    Wk, bk, dk, 1);
    sgemm_tn<<<gemm_grid, 256>>>(values,  Wv, bv, dv, 1);
    attn_kernel<<<dim3(4, 32), 128, shb>>>(0);    // bh  0..31
    attn_kernel<<<dim3(4, 32), 128, shb>>>(32);   // bh 32..63
    attn_kernel<<<dim3(4, 32), 128, shb>>>(64);   // bh 64..95
    attn_kernel<<<dim3(4, 32), 128, shb>>>(96);   // bh 96..127
    sgemm_tn<<<gemm_grid, 256>>>(dattn, Wo, bo, out, 0);
}

// round 6
// speedup vs baseline: 1.4767x; 1.0346x over previous
#include <cuda_runtime.h>
#include <cuda_fp16.h>
#include <math.h>

#define Bb 8
#define Hh 16
#define Nn 512
#define Dk 64
#define Dm 1024

typedef unsigned long long ull;

__device__ __forceinline__ ull f2dup(float a) {
    ull r; asm("mov.b64 %0,{%1,%1};" : "=l"(r) : "f"(a)); return r;
}
__device__ __forceinline__ float2 unpack2(ull a) {
    float2 f; asm("mov.b64 {%0,%1},%2;" : "=f"(f.x), "=f"(f.y) : "l"(a)); return f;
}
__device__ __forceinline__ ull ffma2(ull a, ull b, ull c) {
    ull d; asm("fma.rn.f32x2 %0,%1,%2,%3;" : "=l"(d) : "l"(a), "l"(b), "l"(c)); return d;
}
__device__ __forceinline__ ull fmul2(ull a, ull b) {
    ull d; asm("mul.rn.f32x2 %0,%1,%2;" : "=l"(d) : "l"(a), "l"(b)); return d;
}

__device__ float g_q[Bb*Hh*Nn*Dk];
__device__ float g_k[Bb*Hh*Nn*Dk];
__device__ float g_v[Bb*Hh*Nn*Dk];
__device__ __half g_g16[(size_t)Bb*Hh*Nn*Nn];   // g = max(relu(.),1e-6), (b,h,i,j)
__device__ float g_attn[Bb*Nn*Hh*Dk];
__device__ float g_bf[Bb*Nn*40];                // per-box: cx,cy,lw,lh, then 8x{sw,cw,sh,ch}

// ---------------- SGEMM, BK=16 double-buffered, FFMA2 ----------------------
__global__ __launch_bounds__(256) void sgemm_tn(const float* __restrict__ A,
                                                const float* __restrict__ W,
                                                const float* __restrict__ bias,
                                                float* __restrict__ C, int remap) {
    __shared__ __align__(16) float As[2][16][128];
    __shared__ __align__(16) float Bs[2][16][128];
    int tid = threadIdx.x;
    int tx = tid & 15, ty = tid >> 4;
    int m0 = blockIdx.y * 128, n0 = blockIdx.x * 128;
    int lr = tid >> 1, lc = (tid & 1) * 8;
    const float* Ap = A + (size_t)(m0 + lr) * 1024 + lc;
    const float* Wp = W + (size_t)(n0 + lr) * 1024 + lc;

    ull acc[8][4];
#pragma unroll
    for (int i = 0; i < 8; i++)
#pragma unroll
        for (int p = 0; p < 4; p++) acc[i][p] = 0ull;

    float av[8], wv[8];
    {
        float4 x0 = *(const float4*)Ap, x1 = *(const float4*)(Ap+4);
        float4 y0 = *(const float4*)Wp, y1 = *(const float4*)(Wp+4);
        av[0]=x0.x;av[1]=x0.y;av[2]=x0.z;av[3]=x0.w;av[4]=x1.x;av[5]=x1.y;av[6]=x1.z;av[7]=x1.w;
        wv[0]=y0.x;wv[1]=y0.y;wv[2]=y0.z;wv[3]=y0.w;wv[4]=y1.x;wv[5]=y1.y;wv[6]=y1.z;wv[7]=y1.w;
    }
#pragma unroll
    for (int j = 0; j < 8; j++) { As[0][lc+j][lr] = av[j]; Bs[0][lc+j][lr] = wv[j]; }
    __syncthreads();

#pragma unroll 1
    for (int t = 0; t < 64; t++) {
        int cur = t & 1;
        if (t < 63) {
            float4 x0 = *(const float4*)(Ap+(t+1)*16), x1 = *(const float4*)(Ap+(t+1)*16+4);
            float4 y0 = *(const float4*)(Wp+(t+1)*16), y1 = *(const float4*)(Wp+(t+1)*16+4);
            av[0]=x0.x;av[1]=x0.y;av[2]=x0.z;av[3]=x0.w;av[4]=x1.x;av[5]=x1.y;av[6]=x1.z;av[7]=x1.w;
            wv[0]=y0.x;wv[1]=y0.y;wv[2]=y0.z;wv[3]=y0.w;wv[4]=y1.x;wv[5]=y1.y;wv[6]=y1.z;wv[7]=y1.w;
        }
#pragma unroll
        for (int kk = 0; kk < 16; kk++) {
            float4 a0 = *(const float4*)&As[cur][kk][ty*4];
            float4 a1 = *(const float4*)&As[cur][kk][64+ty*4];
            ull ad[8] = {f2dup(a0.x),f2dup(a0.y),f2dup(a0.z),f2dup(a0.w),
                         f2dup(a1.x),f2dup(a1.y),f2dup(a1.z),f2dup(a1.w)};
            ulonglong2 b0 = *(const ulonglong2*)&Bs[cur][kk][tx*4];
            ulonglong2 b1 = *(const ulonglong2*)&Bs[cur][kk][64+tx*4];
            ull bp[4] = {b0.x, b0.y, b1.x, b1.y};
#pragma unroll
            for (int i = 0; i < 8; i++)
#pragma unroll
                for (int p = 0; p < 4; p++)
                    acc[i][p] = ffma2(ad[i], bp[p], acc[i][p]);
        }
        if (t < 63) {
#pragma unroll
            for (int j = 0; j < 8; j++) { As[cur^1][lc+j][lr] = av[j]; Bs[cur^1][lc+j][lr] = wv[j]; }
        }
        __syncthreads();
    }
#pragma unroll
    for (int i = 0; i < 8; i++) {
        int mrow = m0 + ((i < 4) ? (ty*4+i) : (64+ty*4+(i-4)));
#pragma unroll
        for (int jq = 0; jq < 2; jq++) {
            int ncol = n0 + ((jq==0) ? (tx*4) : (64+tx*4));
            float2 u0 = unpack2(acc[i][jq*2+0]);
            float2 u1 = unpack2(acc[i][jq*2+1]);
            float4 v;
            v.x = u0.x + bias[ncol+0]; v.y = u0.y + bias[ncol+1];
            v.z = u1.x + bias[ncol+2]; v.w = u1.y + bias[ncol+3];
            if (remap) {
                int bb = mrow>>9, n = mrow&511, hh = ncol>>6, d = ncol&63;
                *(float4*)&C[(((size_t)bb*Hh+hh)*Nn+n)*Dk+d] = v;
            } else {
                *(float4*)&C[(size_t)mrow*1024+ncol] = v;
            }
        }
    }
}

// ---------------- per-box feature tables (trivial cost) --------------------
__global__ __launch_bounds__(512) void box_feat_kernel(const float* __restrict__ boxes) {
    int b = blockIdx.x, i = threadIdx.x;
    const float* p = boxes + ((size_t)b*Nn+i)*4;
    float x0=p[0], y0=p[1], x1=p[2], y1=p[3];
    float cx=0.5f*(x0+x1), cy=0.5f*(y0+y1);
    float w=x1-x0+1.0f, h=y1-y0+1.0f;
    float lw=__logf(w), lh=__logf(h);
    float* o = g_bf + ((size_t)b*Nn+i)*40;
    o[0]=cx; o[1]=cy; o[2]=lw; o[3]=lh;
    const float dm[8] = {1.0f,0.421696503429f,0.177827941004f,0.0749894209332f,
                         0.0316227766017f,0.0133352143216f,0.00562341325190f,0.00237137370566f};
#pragma unroll
    for (int f = 0; f < 8; f++) {
        float sw, cw, sh, ch;
        __sincosf(100.0f*dm[f]*lw, &sw, &cw);
        __sincosf(100.0f*dm[f]*lh, &sh, &ch);
        *(float4*)&o[4 + f*4] = make_float4(sw, cw, sh, ch);
    }
}

// ---------------- geometry bias: separable dw/dh, MUFU only for dx/dy ------
__global__ __launch_bounds__(128) void geo_bias_kernel(const float* __restrict__ Wg,
                                                       const float* __restrict__ bg) {
    __shared__ __align__(16) float Wsin[32][16];
    __shared__ __align__(16) float Wcos[32][16];
    __shared__ float bgs[16];
    int i = blockIdx.x, b = blockIdx.y;
    int tid = threadIdx.x;

    for (int t = tid; t < Hh*64; t += 128) {
        int h = t >> 6, d = t & 63;
        float w = Wg[h*64+d];
        if (d < 32) Wsin[d][h] = w; else Wcos[d-32][h] = w;
    }
    if (tid < 16) bgs[tid] = bg[tid];

    const float* fi = g_bf + ((size_t)b*Nn+i)*40;
    float cxi = fi[0], cyi = fi[1], lwi = fi[2], lhi = fi[3];
    float swi[8], cwi[8], shi[8], chi[8];
#pragma unroll
    for (int f = 0; f < 8; f++) {
        float4 v = *(const float4*)&fi[4 + f*4];
        swi[f]=v.x; cwi[f]=v.y; shi[f]=v.z; chi[f]=v.w;
    }
    __syncthreads();

    const float dm[8] = {1.0f,0.421696503429f,0.177827941004f,0.0749894209332f,
                         0.0316227766017f,0.0133352143216f,0.00562341325190f,0.00237137370566f};
    const float C0 = -6.90775527898f;   // log(1e-3)

    for (int j = tid; j < Nn; j += 128) {
        const float* fj = g_bf + ((size_t)b*Nn+j)*40;
        float4 h0 = *(const float4*)fj;      // cxj, cyj, lwj, lhj (lwj/lhj unused)
        float ux = fmaxf(__logf(fabsf(cxi - h0.x)) - lwi, C0);
        float uy = fmaxf(__logf(fabsf(cyi - h0.y)) - lhi, C0);

        float acc[16];
#pragma unroll
        for (int h = 0; h < 16; h++) acc[h] = bgs[h];

#pragma unroll
        for (int f = 0; f < 8; f++) {
            float sx, cx_, sy, cy_;
            __sincosf(100.0f*dm[f]*ux, &sx, &cx_);
            __sincosf(100.0f*dm[f]*uy, &sy, &cy_);
            float4 tj = *(const float4*)&fj[4 + f*4];   // swj, cwj, shj, chj
            float sw_ = swi[f]*tj.y - cwi[f]*tj.x;
            float cw_ = cwi[f]*tj.y + swi[f]*tj.x;
            float sh_ = shi[f]*tj.w - chi[f]*tj.z;
            float ch_ = chi[f]*tj.w + shi[f]*tj.z;
            float sv[4] = {sx, sy, sw_, sh_};
            float cv[4] = {cx_, cy_, cw_, ch_};
#pragma unroll
            for (int c = 0; c < 4; c++) {
                int idx = c*8 + f;
                float s = sv[c], cc = cv[c];
#pragma unroll
                for (int hq = 0; hq < 4; hq++) {
                    float4 ws = *(const float4*)&Wsin[idx][hq*4];
                    float4 wc = *(const float4*)&Wcos[idx][hq*4];
                    acc[hq*4+0] += s*ws.x + cc*wc.x;
                    acc[hq*4+1] += s*ws.y + cc*wc.y;
                    acc[hq*4+2] += s*ws.z + cc*wc.z;
                    acc[hq*4+3] += s*ws.w + cc*wc.w;
                }
            }
        }
#pragma unroll
        for (int h = 0; h < 16; h++)
            g_g16[(((size_t)b*Hh+h)*Nn+i)*Nn+j] = __float2half_rn(fmaxf(acc[h], 1e-6f));
    }
}

// ---------------- flash attention (unchanged from R4) ----------------------
#define PT_RO(q) ((q)*72 + ((q)>>3)*8)
__global__ __launch_bounds__(128) void attn_kernel(int bh0) {
    extern __shared__ float sh[];
    float* Qs  = sh;
    float* Kt  = sh + 64*132;
    float* Vt  = Kt + 64*68;
    float* Ptq = Vt + 64*68;

    int bh = bh0 + blockIdx.y;
    int b = bh >> 4, h = bh & 15;
    int q0 = blockIdx.x * 128;
    const float* Qg = g_q + ((size_t)bh*Nn + q0)*Dk;
    const float* Kg = g_k + (size_t)bh*Nn*Dk;
    const float* Vg = g_v + (size_t)bh*Nn*Dk;
    const __half* Gg = g_g16 + ((size_t)bh*Nn + q0)*Nn;

    int tid = threadIdx.x;
    int tx = tid & 7, qs = tid >> 3;

    for (int tt = tid; tt < 512; tt += 128) {
        int qb = (tt & 31)*4, d0 = (tt >> 5)*4;
        float4 r0 = *(const float4*)&Qg[(qb+0)*64+d0];
        float4 r1 = *(const float4*)&Qg[(qb+1)*64+d0];
        float4 r2 = *(const float4*)&Qg[(qb+2)*64+d0];
        float4 r3 = *(const float4*)&Qg[(qb+3)*64+d0];
        *(float4*)&Qs[(d0+0)*132+qb] = make_float4(r0.x,r1.x,r2.x,r3.x);
        *(float4*)&Qs[(d0+1)*132+qb] = make_float4(r0.y,r1.y,r2.y,r3.y);
        *(float4*)&Qs[(d0+2)*132+qb] = make_float4(r0.z,r1.z,r2.z,r3.z);
        *(float4*)&Qs[(d0+3)*132+qb] = make_float4(r0.w,r1.w,r2.w,r3.w);
    }

    float m[8], l[8];
    ull o[8][4];
#pragma unroll
    for (int i = 0; i < 8; i++) {
        m[i] = -1e30f; l[i] = 0.f;
#pragma unroll
        for (int p = 0; p < 4; p++) o[i][p] = 0ull;
    }
    int ro[8];
#pragma unroll
    for (int qq = 0; qq < 8; qq++) ro[qq] = PT_RO(qs*8+qq);

    for (int kt = 0; kt < 8; kt++) {
        __syncthreads();
        for (int tt = tid; tt < 256; tt += 128) {
            int kb = (tt & 15)*4, d0 = (tt >> 4)*4;
            const float* Kb = Kg + (size_t)(kt*64)*Dk;
            float4 r0 = *(const float4*)&Kb[(kb+0)*64+d0];
            float4 r1 = *(const float4*)&Kb[(kb+1)*64+d0];
            float4 r2 = *(const float4*)&Kb[(kb+2)*64+d0];
            float4 r3 = *(const float4*)&Kb[(kb+3)*64+d0];
            *(float4*)&Kt[(d0+0)*68+kb] = make_float4(r0.x,r1.x,r2.x,r3.x);
            *(float4*)&Kt[(d0+1)*68+kb] = make_float4(r0.y,r1.y,r2.y,r3.y);
            *(float4*)&Kt[(d0+2)*68+kb] = make_float4(r0.z,r1.z,r2.z,r3.z);
            *(float4*)&Kt[(d0+3)*68+kb] = make_float4(r0.w,r1.w,r2.w,r3.w);
        }
        for (int i = tid; i < 1024; i += 128) {
            int r = i >> 4, c = (i & 15)*4;
            *(float4*)&Vt[r*68+c] = *(const float4*)&Vg[(size_t)(kt*64+r)*64+c];
        }
        __syncthreads();

        ull acc[8][4];
#pragma unroll
        for (int i = 0; i < 8; i++)
#pragma unroll
            for (int p = 0; p < 4; p++) acc[i][p] = 0ull;
#pragma unroll 2
        for (int d = 0; d < 64; d++) {
            float4 a0 = *(const float4*)&Qs[d*132 + qs*8];
            float4 a1 = *(const float4*)&Qs[d*132 + qs*8 + 4];
            ull qd[8] = {f2dup(a0.x),f2dup(a0.y),f2dup(a0.z),f2dup(a0.w),
                         f2dup(a1.x),f2dup(a1.y),f2dup(a1.z),f2dup(a1.w)};
            ulonglong2 k0 = *(const ulonglong2*)&Kt[d*68 + tx*8];
            ulonglong2 k1 = *(const ulonglong2*)&Kt[d*68 + tx*8 + 4];
            ull kp[4] = {k0.x, k0.y, k1.x, k1.y};
#pragma unroll
            for (int i = 0; i < 8; i++)
#pragma unroll
                for (int p = 0; p < 4; p++)
                    acc[i][p] = ffma2(qd[i], kp[p], acc[i][p]);
        }

#pragma unroll
        for (int qq = 0; qq < 8; qq++) {
            float s[8];
#pragma unroll
            for (int p = 0; p < 4; p++) {
                float2 u = unpack2(acc[qq][p]);
                s[2*p] = u.x*0.125f; s[2*p+1] = u.y*0.125f;
            }
            float mt = s[0];
#pragma unroll
            for (int j = 1; j < 8; j++) mt = fmaxf(mt, s[j]);
            mt = fmaxf(mt, __shfl_xor_sync(0xffffffffu, mt, 1, 8));
            mt = fmaxf(mt, __shfl_xor_sync(0xffffffffu, mt, 2, 8));
            mt = fmaxf(mt, __shfl_xor_sync(0xffffffffu, mt, 4, 8));
            float mn = fmaxf(m[qq], mt);
            float resc = __expf(m[qq] - mn);
            m[qq] = mn;
            l[qq] *= resc;
            ull rd = f2dup(resc);
#pragma unroll
            for (int p = 0; p < 4; p++) o[qq][p] = fmul2(o[qq][p], rd);

            const __half* gp = Gg + (size_t)(qs*8+qq)*Nn + kt*64 + tx*8;
            uint4 gv = *(const uint4*)gp;
            float2 g0 = __half22float2(*(__half2*)&gv.x);
            float2 g1 = __half22float2(*(__half2*)&gv.y);
            float2 g2 = __half22float2(*(__half2*)&gv.z);
            float2 g3 = __half22float2(*(__half2*)&gv.w);
            float w0 = g0.x*__expf(s[0]-mn), w1 = g0.y*__expf(s[1]-mn);
            float w2 = g1.x*__expf(s[2]-mn), w3 = g1.y*__expf(s[3]-mn);
            float w4 = g2.x*__expf(s[4]-mn), w5 = g2.y*__expf(s[5]-mn);
            float w6 = g3.x*__expf(s[6]-mn), w7 = g3.y*__expf(s[7]-mn);
            float ps = ((w0+w1)+(w2+w3)) + ((w4+w5)+(w6+w7));
            ps += __shfl_xor_sync(0xffffffffu, ps, 1, 8);
            ps += __shfl_xor_sync(0xffffffffu, ps, 2, 8);
            ps += __shfl_xor_sync(0xffffffffu, ps, 4, 8);
            l[qq] += ps;
            *(float4*)&Ptq[ro[qq] + tx*8]     = make_float4(w0,w1,w2,w3);
            *(float4*)&Ptq[ro[qq] + tx*8 + 4] = make_float4(w4,w5,w6,w7);
        }
        __syncthreads();

#pragma unroll 2
        for (int k = 0; k < 64; k++) {
            ull pd[8];
#pragma unroll
            for (int qq = 0; qq < 8; qq++) pd[qq] = f2dup(Ptq[ro[qq] + k]);
            ulonglong2 v0 = *(const ulonglong2*)&Vt[k*68 + tx*8];
            ulonglong2 v1 = *(const ulonglong2*)&Vt[k*68 + tx*8 + 4];
            ull vp[4] = {v0.x, v0.y, v1.x, v1.y};
#pragma unroll
            for (int i = 0; i < 8; i++)
#pragma unroll
                for (int p = 0; p < 4; p++)
                    o[i][p] = ffma2(pd[i], vp[p], o[i][p]);
        }
    }

#pragma unroll
    for (int qq = 0; qq < 8; qq++) {
        float inv = 1.0f / l[qq];
        int row = q0 + qs*8 + qq;
        float2 u0 = unpack2(o[qq][0]), u1 = unpack2(o[qq][1]);
        float2 u2 = unpack2(o[qq][2]), u3 = unpack2(o[qq][3]);
        size_t base = ((size_t)b*Nn+row)*Dm + h*64 + tx*8;
        *(float4*)&g_attn[base]   = make_float4(u0.x*inv, u0.y*inv, u1.x*inv, u1.y*inv);
        *(float4*)&g_attn[base+4] = make_float4(u2.x*inv, u2.y*inv, u3.x*inv, u3.y*inv);
    }
}

// ---------------------------------------------------------------------------
extern "C" void kernel_launch(void* const* d_in, const int* in_sizes, int n_in,
                              void* d_out, int out_size) {
    (void)in_sizes; (void)n_in; (void)out_size;
    const float* queries = (const float*)d_in[0];
    const float* keys    = (const float*)d_in[1];
    const float* values  = (const float*)d_in[2];
    const float* boxes   = (const float*)d_in[3];
    const float* Wq = (const float*)d_in[4];
    const float* bq = (const float*)d_in[5];
    const float* Wk = (const float*)d_in[6];
    const float* bk = (const float*)d_in[7];
    const float* Wv = (const float*)d_in[8];
    const float* bv = (const float*)d_in[9];
    const float* Wo = (const float*)d_in[10];
    const float* bo = (const float*)d_in[11];
    const float* Wg = (const float*)d_in[12];
    const float* bg = (const float*)d_in[13];
    float* out = (float*)d_out;

    float *dq=nullptr, *dk=nullptr, *dv=nullptr, *dattn=nullptr;
    cudaGetSymbolAddress((void**)&dq, g_q);
    cudaGetSymbolAddress((void**)&dk, g_k);
    cudaGetSymbolAddress((void**)&dv, g_v);
    cudaGetSymbolAddress((void**)&dattn, g_attn);

    size_t shb = (size_t)(64*132 + 64*68 + 64*68 + 128*72 + 128) * sizeof(float);
    cudaFuncSetAttribute(attn_kernel, cudaFuncAttributeMaxDynamicSharedMemorySize, (int)shb);

    dim3 gemm_grid(Dm/128, (Bb*Nn)/128);

    box_feat_kernel<<<Bb, 512>>>(boxes);
    geo_bias_kernel<<<dim3(Nn, Bb), 128>>>(Wg, bg);
    sgemm_tn<<<gemm_grid, 256>>>(queries, Wq, bq, dq, 1);
    sgemm_tn<<<gemm_grid, 256>>>(keys,    Wk, bk, dk, 1);
    sgemm_tn<<<gemm_grid, 256>>>(values,  Wv, bv, dv, 1);
    attn_kernel<<<dim3(4, 32), 128, shb>>>(0);
    attn_kernel<<<dim3(4, 32), 128, shb>>>(32);
    attn_kernel<<<dim3(4, 32), 128, shb>>>(64);
    attn_kernel<<<dim3(4, 32), 128, shb>>>(96);
    sgemm_tn<<<gemm_grid, 256>>>(dattn, Wo, bo, out, 0);
}